// round 2
// baseline (speedup 1.0000x reference)
#include <cuda_runtime.h>
#include <math.h>

#define S_LEN 1024
#define BATCH 8
#define DMODEL 768
#define NHEAD 12
#define HDIM 64
#define MROWS (S_LEN * BATCH)          // 8192
#define SBD ((size_t)S_LEN * BATCH * DMODEL)  // 6291456

// scratch for attention mix output, layout [r = s*B+b][d = h*64+dh]
__device__ float g_mix[(size_t)MROWS * DMODEL];

// ----------------------------------------------------------------------------
// GEMM: C[r, n] = sum_k A[r,k] * W[n,k] + bias[n]
// Output columns are split into regions of 768: column n goes to
//   C + (n/768)*region_stride + r*768 + (n%768)
// (region_stride = SBD for the QKV projection -> q,k,v regions; for the out
//  projection N=768 so region is always 0.)
// Tiling: 128x128 block, BK=16, 256 threads, 8x8 per-thread micro tile.
// ----------------------------------------------------------------------------
__global__ __launch_bounds__(256) void gemm_bias_kernel(
    const float* __restrict__ A, const float* __restrict__ W,
    const float* __restrict__ bias, float* __restrict__ C,
    int K, size_t region_stride)
{
    __shared__ float As[16][132];
    __shared__ float Bs[16][132];

    const int tid = threadIdx.x;
    const int tx = tid & 15;       // 0..15 -> 8 output cols
    const int ty = tid >> 4;       // 0..15 -> 8 output rows
    const int row0 = blockIdx.y * 128;
    const int col0 = blockIdx.x * 128;

    const float* Ab = A + (size_t)row0 * K;
    const float* Wb = W + (size_t)col0 * K;

    float acc[8][8];
#pragma unroll
    for (int i = 0; i < 8; i++)
#pragma unroll
        for (int j = 0; j < 8; j++) acc[i][j] = 0.0f;

    for (int kt = 0; kt < K; kt += 16) {
        // Load A tile (128 rows x 16 k) and W tile (128 cols x 16 k), both
        // stored transposed into smem as [k][mn]. 512 float4 each; 2/thread.
#pragma unroll
        for (int i = 0; i < 2; i++) {
            int f = tid + i * 256;
            int r = f >> 2;
            int cv = (f & 3) * 4;
            float4 v = *(const float4*)(Ab + (size_t)r * K + kt + cv);
            As[cv + 0][r] = v.x; As[cv + 1][r] = v.y;
            As[cv + 2][r] = v.z; As[cv + 3][r] = v.w;
        }
#pragma unroll
        for (int i = 0; i < 2; i++) {
            int f = tid + i * 256;
            int r = f >> 2;
            int cv = (f & 3) * 4;
            float4 v = *(const float4*)(Wb + (size_t)r * K + kt + cv);
            Bs[cv + 0][r] = v.x; Bs[cv + 1][r] = v.y;
            Bs[cv + 2][r] = v.z; Bs[cv + 3][r] = v.w;
        }
        __syncthreads();

#pragma unroll
        for (int k = 0; k < 16; k++) {
            float4 a0 = *(const float4*)&As[k][ty * 8];
            float4 a1 = *(const float4*)&As[k][ty * 8 + 4];
            float4 b0 = *(const float4*)&Bs[k][tx * 8];
            float4 b1 = *(const float4*)&Bs[k][tx * 8 + 4];
            float a[8] = {a0.x, a0.y, a0.z, a0.w, a1.x, a1.y, a1.z, a1.w};
            float b[8] = {b0.x, b0.y, b0.z, b0.w, b1.x, b1.y, b1.z, b1.w};
#pragma unroll
            for (int i = 0; i < 8; i++)
#pragma unroll
                for (int j = 0; j < 8; j++)
                    acc[i][j] = fmaf(a[i], b[j], acc[i][j]);
        }
        __syncthreads();
    }

    // epilogue: bias + region scatter (8-col span never crosses a 768 boundary)
    const int cbase = col0 + tx * 8;
    const int region = cbase / DMODEL;
    const int cc = cbase - region * DMODEL;
    float bv[8];
#pragma unroll
    for (int j = 0; j < 8; j++) bv[j] = bias[cbase + j];
    float* Cr = C + region * region_stride + cc;
#pragma unroll
    for (int i = 0; i < 8; i++) {
        int r = row0 + ty * 8 + i;
        float4 o0, o1;
        o0.x = acc[i][0] + bv[0]; o0.y = acc[i][1] + bv[1];
        o0.z = acc[i][2] + bv[2]; o0.w = acc[i][3] + bv[3];
        o1.x = acc[i][4] + bv[4]; o1.y = acc[i][5] + bv[5];
        o1.z = acc[i][6] + bv[6]; o1.w = acc[i][7] + bv[7];
        *(float4*)(Cr + (size_t)r * DMODEL) = o0;
        *(float4*)(Cr + (size_t)r * DMODEL + 4) = o1;
    }
}

// ----------------------------------------------------------------------------
// Flash-style attention. One block = 64 query rows of one (batch, head).
// 128 threads: tx = tid&7 (8 key/dh cols of 8), ty = tid>>3 (16 row groups of 4).
// q/k/v are read from the (S, B, H*DH) output regions (index (s*B+b)*768+h*64+dh).
// mix written to g_mix[(s*B+b)*768 + h*64 + dh].
// Masking: key >= 1016 is masked (-10000) when query==0 or query>=1016.
// ----------------------------------------------------------------------------
__global__ __launch_bounds__(128) void attn_kernel(
    const float* __restrict__ qg, const float* __restrict__ kg,
    const float* __restrict__ vg, float* __restrict__ mix)
{
    const int ST = 68;                 // padded smem row stride (floats)
    extern __shared__ float sm[];
    float* Qs = sm;                    // [64][68]
    float* Ks = Qs + 64 * ST;          // [64][68]  (reused as P after scores)
    float* Vt = Ks + 64 * ST;          // [64][68]  V transposed: [dh][key]
    float* mrow = Vt + 64 * ST;        // [64]
    float* lrow = mrow + 64;           // [64]
    float* frow = lrow + 64;           // [64]
    float* red  = frow + 64;           // [64][8]

    const int tid = threadIdx.x;
    const int tx = tid & 7;
    const int ty = tid >> 3;
    const int bh = blockIdx.y;
    const int b = bh / NHEAD;
    const int h = bh - b * NHEAD;
    const int q0 = blockIdx.x * 64;
    const size_t rstride = (size_t)BATCH * DMODEL;   // 6144

    const float* qbase = qg + (size_t)q0 * rstride + (size_t)b * DMODEL + h * HDIM;
    const float* kbase = kg + (size_t)b * DMODEL + h * HDIM;
    const float* vbase = vg + (size_t)b * DMODEL + h * HDIM;

    // load Q tile (64 x 64), 1024 float4 / 128 threads
#pragma unroll
    for (int i = 0; i < 8; i++) {
        int f = tid + i * 128;
        int r = f >> 4, c4 = (f & 15) * 4;
        *(float4*)(Qs + r * ST + c4) = *(const float4*)(qbase + (size_t)r * rstride + c4);
    }
    if (tid < 64) { mrow[tid] = -1e30f; lrow[tid] = 0.0f; }

    bool qm[4];
#pragma unroll
    for (int i = 0; i < 4; i++) {
        int qr = q0 + ty * 4 + i;
        qm[i] = (qr == 0) || (qr >= S_LEN - 8);
    }

    float acc[4][8];
#pragma unroll
    for (int i = 0; i < 4; i++)
#pragma unroll
        for (int j = 0; j < 8; j++) acc[i][j] = 0.0f;

    __syncthreads();

    for (int kt = 0; kt < S_LEN; kt += 64) {
        // load K tile [key][dh]
#pragma unroll
        for (int i = 0; i < 8; i++) {
            int f = tid + i * 128;
            int r = f >> 4, c4 = (f & 15) * 4;
            *(float4*)(Ks + r * ST + c4) =
                *(const float4*)(kbase + (size_t)(kt + r) * rstride + c4);
        }
        // load V tile transposed: Vt[dh][key]
#pragma unroll
        for (int i = 0; i < 8; i++) {
            int f = tid + i * 128;
            int r = f >> 4, c4 = (f & 15) * 4;
            float4 v = *(const float4*)(vbase + (size_t)(kt + r) * rstride + c4);
            Vt[(c4 + 0) * ST + r] = v.x;
            Vt[(c4 + 1) * ST + r] = v.y;
            Vt[(c4 + 2) * ST + r] = v.z;
            Vt[(c4 + 3) * ST + r] = v.w;
        }
        __syncthreads();  // (A)

        // scores: s[i][j] = (Q row . K col) * 0.125 with masking
        float s[4][8];
#pragma unroll
        for (int i = 0; i < 4; i++)
#pragma unroll
            for (int j = 0; j < 8; j++) s[i][j] = 0.0f;

#pragma unroll
        for (int kk = 0; kk < HDIM; kk += 4) {
            float4 qf[4], kf[8];
#pragma unroll
            for (int i = 0; i < 4; i++)
                qf[i] = *(const float4*)(Qs + (ty * 4 + i) * ST + kk);
#pragma unroll
            for (int j = 0; j < 8; j++)
                kf[j] = *(const float4*)(Ks + (tx * 8 + j) * ST + kk);
#pragma unroll
            for (int i = 0; i < 4; i++)
#pragma unroll
                for (int j = 0; j < 8; j++) {
                    s[i][j] = fmaf(qf[i].x, kf[j].x, s[i][j]);
                    s[i][j] = fmaf(qf[i].y, kf[j].y, s[i][j]);
                    s[i][j] = fmaf(qf[i].z, kf[j].z, s[i][j]);
                    s[i][j] = fmaf(qf[i].w, kf[j].w, s[i][j]);
                }
        }
#pragma unroll
        for (int i = 0; i < 4; i++) {
            float pm = -1e30f;
#pragma unroll
            for (int j = 0; j < 8; j++) {
                int kgl = kt + tx * 8 + j;
                float v = s[i][j] * 0.125f;
                if (kgl >= S_LEN - 8 && qm[i]) v = -10000.0f;
                s[i][j] = v;
                pm = fmaxf(pm, v);
            }
            red[(ty * 4 + i) * 8 + tx] = pm;
        }
        __syncthreads();  // (B)

        if (tid < 64) {
            float mo = mrow[tid];
            float tm = mo;
#pragma unroll
            for (int t = 0; t < 8; t++) tm = fmaxf(tm, red[tid * 8 + t]);
            float f = __expf(mo - tm);
            mrow[tid] = tm;
            frow[tid] = f;
            lrow[tid] *= f;
        }
        __syncthreads();  // (C)

        // exponentiate, write P into Ks, partial sums, rescale O
#pragma unroll
        for (int i = 0; i < 4; i++) {
            int r = ty * 4 + i;
            float mn = mrow[r];
            float fr = frow[r];
            float ps = 0.0f;
            float p[8];
#pragma unroll
            for (int j = 0; j < 8; j++) {
                p[j] = __expf(s[i][j] - mn);
                ps += p[j];
            }
            red[r * 8 + tx] = ps;
            float4 p0 = make_float4(p[0], p[1], p[2], p[3]);
            float4 p1 = make_float4(p[4], p[5], p[6], p[7]);
            *(float4*)(Ks + r * ST + tx * 8) = p0;
            *(float4*)(Ks + r * ST + tx * 8 + 4) = p1;
#pragma unroll
            for (int j = 0; j < 8; j++) acc[i][j] *= fr;
        }
        __syncthreads();  // (D)

        if (tid < 64) {
            float ssum = 0.0f;
#pragma unroll
            for (int t = 0; t < 8; t++) ssum += red[tid * 8 + t];
            lrow[tid] += ssum;
        }

        // O += P * V  (P in Ks[row][key], V in Vt[dh][key])
#pragma unroll
        for (int kk = 0; kk < 64; kk += 4) {
            float4 pf[4], vf[8];
#pragma unroll
            for (int i = 0; i < 4; i++)
                pf[i] = *(const float4*)(Ks + (ty * 4 + i) * ST + kk);
#pragma unroll
            for (int j = 0; j < 8; j++)
                vf[j] = *(const float4*)(Vt + (tx * 8 + j) * ST + kk);
#pragma unroll
            for (int i = 0; i < 4; i++)
#pragma unroll
                for (int j = 0; j < 8; j++) {
                    acc[i][j] = fmaf(pf[i].x, vf[j].x, acc[i][j]);
                    acc[i][j] = fmaf(pf[i].y, vf[j].y, acc[i][j]);
                    acc[i][j] = fmaf(pf[i].z, vf[j].z, acc[i][j]);
                    acc[i][j] = fmaf(pf[i].w, vf[j].w, acc[i][j]);
                }
        }
        __syncthreads();  // (E) protect Ks/Vt for next tile
    }

    // epilogue: normalize and write mix
#pragma unroll
    for (int i = 0; i < 4; i++) {
        int r = ty * 4 + i;
        int qr = q0 + r;
        float inv = 1.0f / lrow[r];
        float* dst = mix + ((size_t)qr * BATCH + b) * DMODEL + h * HDIM + tx * 8;
        float4 o0, o1;
        o0.x = acc[i][0] * inv; o0.y = acc[i][1] * inv;
        o0.z = acc[i][2] * inv; o0.w = acc[i][3] * inv;
        o1.x = acc[i][4] * inv; o1.y = acc[i][5] * inv;
        o1.z = acc[i][6] * inv; o1.w = acc[i][7] * inv;
        *(float4*)(dst) = o0;
        *(float4*)(dst + 4) = o1;
    }
}

extern "C" void kernel_launch(void* const* d_in, const int* in_sizes, int n_in,
                              void* d_out, int out_size)
{
    const float* x      = (const float*)d_in[0];  // (S, B, D)
    const float* w_in   = (const float*)d_in[1];  // (3D, D)
    const float* b_in   = (const float*)d_in[2];  // (3D,)
    const float* w_out  = (const float*)d_in[3];  // (D, D)
    const float* b_out  = (const float*)d_in[4];  // (D,)
    float* out = (float*)d_out;

    float* q_out   = out;            // (S, B, H, DH) == [r][d]
    float* o_out   = out + 3 * SBD;  // (S, B, D)     == [r][d]

    float* mix_ptr = nullptr;
    cudaGetSymbolAddress((void**)&mix_ptr, g_mix);

    // 1) QKV projection: M=8192, N=2304, K=768; scatter into q/k/v regions
    {
        dim3 grid(3 * DMODEL / 128, MROWS / 128);
        gemm_bias_kernel<<<grid, 256>>>(x, w_in, b_in, q_out, DMODEL, SBD);
    }

    // 2) attention
    {
        int smem = (3 * 64 * 68 + 3 * 64 + 64 * 8) * (int)sizeof(float);
        cudaFuncSetAttribute(attn_kernel, cudaFuncAttributeMaxDynamicSharedMemorySize, smem);
        dim3 grid(S_LEN / 64, BATCH * NHEAD);
        attn_kernel<<<grid, 128, smem>>>(q_out, q_out + SBD, q_out + 2 * SBD, mix_ptr);
    }

    // 3) output projection: M=8192, N=768, K=768
    {
        dim3 grid(DMODEL / 128, MROWS / 128);
        gemm_bias_kernel<<<grid, 256>>>(mix_ptr, w_out, b_out, o_out, DMODEL, 0);
    }
}

// round 4
// speedup vs baseline: 2.7523x; 2.7523x over previous
#include <cuda_runtime.h>
#include <math.h>

#define S_LEN 1024
#define BATCH 8
#define DMODEL 768
#define NHEAD 12
#define HDIM 64
#define PROMPT_NUM 8
#define TOKENS (S_LEN - PROMPT_NUM)           // 1016
#define MROWS (S_LEN * BATCH)                 // 8192
#define SBD ((size_t)S_LEN * BATCH * DMODEL)  // 6291456
#define AST 68                                // attention smem row stride

// scratch for attention mix output, layout [r = s*B+b][d = h*64+dh]
__device__ float g_mix[(size_t)MROWS * DMODEL];

// ----------------------------------------------------------------------------
// GEMM: C[r, n] = sum_k A[r,k] * W[n,k] + bias[n]
// Column n scattered to region n/768 at offset region_stride per region.
// 128x128 tile, BK=16, 256 threads, 8x8 micro tile (rows {ty*4, 64+ty*4},
// cols {tx*4, 64+tx*4} -> conflict-free float4 fragment loads).
// Double-buffered smem, register prefetch, one sync per k-tile.
// ----------------------------------------------------------------------------
__global__ __launch_bounds__(256, 2) void gemm_bias_kernel(
    const float* __restrict__ A, const float* __restrict__ W,
    const float* __restrict__ bias, float* __restrict__ C,
    int K, size_t region_stride)
{
    __shared__ float As[2][16][132];
    __shared__ float Bs[2][16][132];

    const int tid = threadIdx.x;
    const int tx = tid & 15;
    const int ty = tid >> 4;
    const int row0 = blockIdx.y * 128;
    const int col0 = blockIdx.x * 128;

    const int lr = tid >> 2;          // 0..63
    const int lc = (tid & 3) * 4;     // 0,4,8,12

    const float* Aload0 = A + (size_t)(row0 + lr) * K + lc;
    const float* Aload1 = A + (size_t)(row0 + lr + 64) * K + lc;
    const float* Wload0 = W + (size_t)(col0 + lr) * K + lc;
    const float* Wload1 = W + (size_t)(col0 + lr + 64) * K + lc;

    float acc[8][8];
#pragma unroll
    for (int i = 0; i < 8; i++)
#pragma unroll
        for (int j = 0; j < 8; j++) acc[i][j] = 0.0f;

    float4 pa0, pa1, pb0, pb1;
    pa0 = *(const float4*)(Aload0);
    pa1 = *(const float4*)(Aload1);
    pb0 = *(const float4*)(Wload0);
    pb1 = *(const float4*)(Wload1);

    // store tile 0 into buffer 0 (transposed: [k][mn])
    As[0][lc + 0][lr] = pa0.x; As[0][lc + 1][lr] = pa0.y;
    As[0][lc + 2][lr] = pa0.z; As[0][lc + 3][lr] = pa0.w;
    As[0][lc + 0][lr + 64] = pa1.x; As[0][lc + 1][lr + 64] = pa1.y;
    As[0][lc + 2][lr + 64] = pa1.z; As[0][lc + 3][lr + 64] = pa1.w;
    Bs[0][lc + 0][lr] = pb0.x; Bs[0][lc + 1][lr] = pb0.y;
    Bs[0][lc + 2][lr] = pb0.z; Bs[0][lc + 3][lr] = pb0.w;
    Bs[0][lc + 0][lr + 64] = pb1.x; Bs[0][lc + 1][lr + 64] = pb1.y;
    Bs[0][lc + 2][lr + 64] = pb1.z; Bs[0][lc + 3][lr + 64] = pb1.w;
    __syncthreads();

    for (int kt = 0; kt < K; kt += 16) {
        const int bsel = (kt >> 4) & 1;
        const bool more = (kt + 16) < K;
        if (more) {
            pa0 = *(const float4*)(Aload0 + kt + 16);
            pa1 = *(const float4*)(Aload1 + kt + 16);
            pb0 = *(const float4*)(Wload0 + kt + 16);
            pb1 = *(const float4*)(Wload1 + kt + 16);
        }
#pragma unroll
        for (int k = 0; k < 16; k++) {
            float4 a0 = *(const float4*)&As[bsel][k][ty * 4];
            float4 a1 = *(const float4*)&As[bsel][k][64 + ty * 4];
            float4 b0 = *(const float4*)&Bs[bsel][k][tx * 4];
            float4 b1 = *(const float4*)&Bs[bsel][k][64 + tx * 4];
            float av[8] = {a0.x, a0.y, a0.z, a0.w, a1.x, a1.y, a1.z, a1.w};
            float bv[8] = {b0.x, b0.y, b0.z, b0.w, b1.x, b1.y, b1.z, b1.w};
#pragma unroll
            for (int i = 0; i < 8; i++)
#pragma unroll
                for (int j = 0; j < 8; j++)
                    acc[i][j] = fmaf(av[i], bv[j], acc[i][j]);
        }
        if (more) {
            const int nb = bsel ^ 1;
            As[nb][lc + 0][lr] = pa0.x; As[nb][lc + 1][lr] = pa0.y;
            As[nb][lc + 2][lr] = pa0.z; As[nb][lc + 3][lr] = pa0.w;
            As[nb][lc + 0][lr + 64] = pa1.x; As[nb][lc + 1][lr + 64] = pa1.y;
            As[nb][lc + 2][lr + 64] = pa1.z; As[nb][lc + 3][lr + 64] = pa1.w;
            Bs[nb][lc + 0][lr] = pb0.x; Bs[nb][lc + 1][lr] = pb0.y;
            Bs[nb][lc + 2][lr] = pb0.z; Bs[nb][lc + 3][lr] = pb0.w;
            Bs[nb][lc + 0][lr + 64] = pb1.x; Bs[nb][lc + 1][lr + 64] = pb1.y;
            Bs[nb][lc + 2][lr + 64] = pb1.z; Bs[nb][lc + 3][lr + 64] = pb1.w;
        }
        __syncthreads();
    }

    // epilogue: two col groups, two row groups; each 4-col span stays in one region
    const int cA = col0 + tx * 4;
    const int cB = cA + 64;
    const int regA = cA / DMODEL, ccA = cA - regA * DMODEL;
    const int regB = cB / DMODEL, ccB = cB - regB * DMODEL;
    const float4 bvA = *(const float4*)(bias + cA);
    const float4 bvB = *(const float4*)(bias + cB);
    float* CA = C + regA * region_stride + ccA;
    float* CB = C + regB * region_stride + ccB;
#pragma unroll
    for (int g = 0; g < 2; g++) {
#pragma unroll
        for (int ii = 0; ii < 4; ii++) {
            const int i = g * 4 + ii;
            const size_t r = (size_t)(row0 + g * 64 + ty * 4 + ii) * DMODEL;
            float4 oA, oB;
            oA.x = acc[i][0] + bvA.x; oA.y = acc[i][1] + bvA.y;
            oA.z = acc[i][2] + bvA.z; oA.w = acc[i][3] + bvA.w;
            oB.x = acc[i][4] + bvB.x; oB.y = acc[i][5] + bvB.y;
            oB.z = acc[i][6] + bvB.z; oB.w = acc[i][7] + bvB.w;
            *(float4*)(CA + r) = oA;
            *(float4*)(CB + r) = oB;
        }
    }
}

// ----------------------------------------------------------------------------
// Flash attention v2: one block = 128 query rows of one (batch, head).
// 256 threads: tx = tid&15 owns key/dh cols {tx+j*16}, ty = tid>>4 owns rows
// {ty*8..ty*8+7}. Row softmax state (m,l) replicated in registers across the
// 16 col-owner lanes (contiguous half-warp) -> all reductions are shfl_xor.
// 3 __syncthreads per 64-key tile, no smem reductions, conflict-free column
// fragment loads (lane stride AST=68 floats == 4 mod 32 banks).
// ----------------------------------------------------------------------------
__global__ __launch_bounds__(256, 2) void attn_kernel(
    const float* __restrict__ qg, const float* __restrict__ kg,
    const float* __restrict__ vg, float* __restrict__ mix)
{
    extern __shared__ float sm[];
    float* Qs = sm;                    // [128][AST]
    float* Ks = Qs + 128 * AST;        // [64][AST]   key-major
    float* Vt = Ks + 64 * AST;         // [64][AST]   dh-major (transposed)
    float* Ps = Vt + 64 * AST;         // [128][AST]  probabilities

    const int tid = threadIdx.x;
    const int tx = tid & 15;
    const int ty = tid >> 4;
    const int bh = blockIdx.y;
    const int b = bh / NHEAD;
    const int h = bh - b * NHEAD;
    const int q0 = blockIdx.x * 128;
    const size_t rstride = (size_t)BATCH * DMODEL;   // 6144

    const float* qbase = qg + (size_t)q0 * rstride + (size_t)b * DMODEL + h * HDIM;
    const float* kbase = kg + (size_t)b * DMODEL + h * HDIM;
    const float* vbase = vg + (size_t)b * DMODEL + h * HDIM;

    // load Q tile (128 x 64): 2048 float4 / 256 threads
#pragma unroll
    for (int i = 0; i < 8; i++) {
        int f = tid + i * 256;
        int r = f >> 4, c4 = (f & 15) * 4;
        *(float4*)(Qs + r * AST + c4) = *(const float4*)(qbase + (size_t)r * rstride + c4);
    }

    float mrow[8], lrow[8], acc[8][4];
    bool qm[8];
#pragma unroll
    for (int i = 0; i < 8; i++) {
        mrow[i] = -1e30f; lrow[i] = 0.0f;
        int qr = q0 + ty * 8 + i;
        qm[i] = (qr == 0) || (qr >= TOKENS);
#pragma unroll
        for (int j = 0; j < 4; j++) acc[i][j] = 0.0f;
    }

    for (int kt = 0; kt < S_LEN; kt += 64) {
        // K tile [key][dh]: 1024 float4 / 256 threads
#pragma unroll
        for (int i = 0; i < 4; i++) {
            int f = tid + i * 256;
            int r = f >> 4, c4 = (f & 15) * 4;
            *(float4*)(Ks + r * AST + c4) =
                *(const float4*)(kbase + (size_t)(kt + r) * rstride + c4);
        }
        // V tile transposed: Vt[dh][key]
#pragma unroll
        for (int i = 0; i < 4; i++) {
            int f = tid + i * 256;
            int r = f >> 4, c4 = (f & 15) * 4;
            float4 v = *(const float4*)(vbase + (size_t)(kt + r) * rstride + c4);
            Vt[(c4 + 0) * AST + r] = v.x;
            Vt[(c4 + 1) * AST + r] = v.y;
            Vt[(c4 + 2) * AST + r] = v.z;
            Vt[(c4 + 3) * AST + r] = v.w;
        }
        __syncthreads();  // (1) tiles ready (covers Qs on first iter)

        // scores s[i][j] = Q[row] . K[col]
        float s[8][4];
#pragma unroll
        for (int i = 0; i < 8; i++)
#pragma unroll
            for (int j = 0; j < 4; j++) s[i][j] = 0.0f;

#pragma unroll
        for (int kk = 0; kk < HDIM; kk += 4) {
            float4 kf[4];
#pragma unroll
            for (int j = 0; j < 4; j++)
                kf[j] = *(const float4*)(Ks + (tx + j * 16) * AST + kk);
#pragma unroll
            for (int i = 0; i < 8; i++) {
                float4 qf = *(const float4*)(Qs + (ty * 8 + i) * AST + kk);
#pragma unroll
                for (int j = 0; j < 4; j++) {
                    s[i][j] = fmaf(qf.x, kf[j].x, s[i][j]);
                    s[i][j] = fmaf(qf.y, kf[j].y, s[i][j]);
                    s[i][j] = fmaf(qf.z, kf[j].z, s[i][j]);
                    s[i][j] = fmaf(qf.w, kf[j].w, s[i][j]);
                }
            }
        }

        // scale + mask + per-row max (replicated over 16-lane groups)
        float tm[8];
#pragma unroll
        for (int i = 0; i < 8; i++) {
            float m = -1e30f;
#pragma unroll
            for (int j = 0; j < 4; j++) {
                int kgl = kt + tx + j * 16;
                float v = s[i][j] * 0.125f;
                if (kgl >= TOKENS && qm[i]) v = -10000.0f;
                s[i][j] = v;
                m = fmaxf(m, v);
            }
            tm[i] = m;
        }
#pragma unroll
        for (int o = 1; o < 16; o <<= 1)
#pragma unroll
            for (int i = 0; i < 8; i++)
                tm[i] = fmaxf(tm[i], __shfl_xor_sync(0xffffffffu, tm[i], o));

        float psum[8];
#pragma unroll
        for (int i = 0; i < 8; i++) {
            float nm = fmaxf(mrow[i], tm[i]);
            float f = __expf(mrow[i] - nm);
            mrow[i] = nm;
            lrow[i] *= f;
#pragma unroll
            for (int j = 0; j < 4; j++) acc[i][j] *= f;
            float ps = 0.0f;
#pragma unroll
            for (int j = 0; j < 4; j++) {
                float p = __expf(s[i][j] - nm);
                Ps[(ty * 8 + i) * AST + tx + j * 16] = p;
                ps += p;
            }
            psum[i] = ps;
        }
#pragma unroll
        for (int o = 1; o < 16; o <<= 1)
#pragma unroll
            for (int i = 0; i < 8; i++)
                psum[i] += __shfl_xor_sync(0xffffffffu, psum[i], o);
#pragma unroll
        for (int i = 0; i < 8; i++) lrow[i] += psum[i];
        __syncthreads();  // (2) Ps written

        // O += P * V
#pragma unroll
        for (int kk = 0; kk < 64; kk += 4) {
            float4 vf[4];
#pragma unroll
            for (int j = 0; j < 4; j++)
                vf[j] = *(const float4*)(Vt + (tx + j * 16) * AST + kk);
#pragma unroll
            for (int i = 0; i < 8; i++) {
                float4 pf = *(const float4*)(Ps + (ty * 8 + i) * AST + kk);
#pragma unroll
                for (int j = 0; j < 4; j++) {
                    acc[i][j] = fmaf(pf.x, vf[j].x, acc[i][j]);
                    acc[i][j] = fmaf(pf.y, vf[j].y, acc[i][j]);
                    acc[i][j] = fmaf(pf.z, vf[j].z, acc[i][j]);
                    acc[i][j] = fmaf(pf.w, vf[j].w, acc[i][j]);
                }
            }
        }
        __syncthreads();  // (3) protect Ks/Vt/Ps before next tile
    }

    // epilogue: normalize and write mix (coalesced scalar stores)
#pragma unroll
    for (int i = 0; i < 8; i++) {
        int qr = q0 + ty * 8 + i;
        float inv = 1.0f / lrow[i];
        float* dst = mix + ((size_t)qr * BATCH + b) * DMODEL + h * HDIM;
#pragma unroll
        for (int j = 0; j < 4; j++)
            dst[tx + j * 16] = acc[i][j] * inv;
    }
}

extern "C" void kernel_launch(void* const* d_in, const int* in_sizes, int n_in,
                              void* d_out, int out_size)
{
    const float* x      = (const float*)d_in[0];  // (S, B, D)
    const float* w_in   = (const float*)d_in[1];  // (3D, D)
    const float* b_in   = (const float*)d_in[2];  // (3D,)
    const float* w_out  = (const float*)d_in[3];  // (D, D)
    const float* b_out  = (const float*)d_in[4];  // (D,)
    float* out = (float*)d_out;

    float* q_out = out;            // q/k/v regions: [r=s*B+b][d]
    float* o_out = out + 3 * SBD;  // (S, B, D)

    float* mix_ptr = nullptr;
    cudaGetSymbolAddress((void**)&mix_ptr, g_mix);

    // 1) QKV projection: M=8192, N=2304, K=768
    {
        dim3 grid(3 * DMODEL / 128, MROWS / 128);
        gemm_bias_kernel<<<grid, 256>>>(x, w_in, b_in, q_out, DMODEL, SBD);
    }

    // 2) attention
    {
        int smem = (128 * AST + 64 * AST + 64 * AST + 128 * AST) * (int)sizeof(float);
        cudaFuncSetAttribute(attn_kernel, cudaFuncAttributeMaxDynamicSharedMemorySize, smem);
        dim3 grid(S_LEN / 128, BATCH * NHEAD);
        attn_kernel<<<grid, 256, smem>>>(q_out, q_out + SBD, q_out + 2 * SBD, mix_ptr);
    }

    // 3) output projection: M=8192, N=768, K=768
    {
        dim3 grid(DMODEL / 128, MROWS / 128);
        gemm_bias_kernel<<<grid, 256>>>(mix_ptr, w_out, b_out, o_out, DMODEL, 0);
    }
}

// round 11
// speedup vs baseline: 3.7329x; 1.3563x over previous
#include <cuda_runtime.h>
#include <cuda_bf16.h>
#include <math.h>
#include <stdint.h>

#define S_LEN 1024
#define BATCH 8
#define DMODEL 768
#define NHEAD 12
#define HDIM 64
#define PROMPT_NUM 8
#define TOKENS (S_LEN - PROMPT_NUM)           // 1016
#define MROWS (S_LEN * BATCH)                 // 8192
#define SBD ((size_t)S_LEN * BATCH * DMODEL)  // 6291456
#define AST 68                                // attention smem row stride
#define GK DMODEL                             // K of both GEMMs = 768

// ---------------- bf16 split scratch (allocation-free rule) ----------------
__device__ __nv_bfloat16 g_xh[(size_t)MROWS * GK];
__device__ __nv_bfloat16 g_xl[(size_t)MROWS * GK];
__device__ __nv_bfloat16 g_wih[(size_t)3 * DMODEL * GK];
__device__ __nv_bfloat16 g_wil[(size_t)3 * DMODEL * GK];
__device__ __nv_bfloat16 g_woh[(size_t)DMODEL * GK];
__device__ __nv_bfloat16 g_wol[(size_t)DMODEL * GK];
__device__ __nv_bfloat16 g_mixh[(size_t)MROWS * DMODEL];
__device__ __nv_bfloat16 g_mixl[(size_t)MROWS * DMODEL];

// ---------------- PTX helpers (sm_80-class only: no tcgen05) ----------------
__device__ __forceinline__ uint32_t smem_u32(const void* p) {
    uint32_t a;
    asm("{ .reg .u64 t; cvta.to.shared.u64 t, %1; cvt.u32.u64 %0, t; }" : "=r"(a) : "l"(p));
    return a;
}

#define CP_ASYNC16(dst, src) \
    asm volatile("cp.async.cg.shared.global [%0], [%1], 16;" :: "r"(dst), "l"(src) : "memory")
#define CP_COMMIT() asm volatile("cp.async.commit_group;" ::: "memory")
#define CP_WAIT0() asm volatile("cp.async.wait_group 0;" ::: "memory")
#define CP_WAIT1() asm volatile("cp.async.wait_group 1;" ::: "memory")

__device__ __forceinline__ void ldmx4(uint32_t* r, uint32_t addr) {
    asm volatile("ldmatrix.sync.aligned.m8n8.x4.shared.b16 {%0,%1,%2,%3}, [%4];"
                 : "=r"(r[0]), "=r"(r[1]), "=r"(r[2]), "=r"(r[3]) : "r"(addr));
}
// NON-transposed x2: B tiles are stored [n][k] (k contiguous), which IS the
// col-major B layout mma.row.col expects. R9/R10 bug was using .trans here,
// which swaps the n/k fragment distribution deterministically.
__device__ __forceinline__ void ldmx2(uint32_t* r, uint32_t addr) {
    asm volatile("ldmatrix.sync.aligned.m8n8.x2.shared.b16 {%0,%1}, [%2];"
                 : "=r"(r[0]), "=r"(r[1]) : "r"(addr));
}
__device__ __forceinline__ void mma_bf16(float* c, const uint32_t* a, const uint32_t* b) {
    asm volatile(
        "mma.sync.aligned.m16n8k16.row.col.f32.bf16.bf16.f32 "
        "{%0,%1,%2,%3}, {%4,%5,%6,%7}, {%8,%9}, {%0,%1,%2,%3};"
        : "+f"(c[0]), "+f"(c[1]), "+f"(c[2]), "+f"(c[3])
        : "r"(a[0]), "r"(a[1]), "r"(a[2]), "r"(a[3]), "r"(b[0]), "r"(b[1]));
}

// smem tile geometry: [128 rows][40 bf16] (32 data + 8 pad) = 80 B/row, 10240 B/array
#define TROW 80
#define TBYTES 10240
#define STAGE (4 * TBYTES)   // Ah, Al, Bh, Bl per stage = 40960

// ---------------- fp32 -> bf16 hi/lo split ----------------
__global__ __launch_bounds__(256) void convert_split_kernel(
    const float* __restrict__ in, __nv_bfloat16* __restrict__ hi,
    __nv_bfloat16* __restrict__ lo, int n4)
{
    int i = blockIdx.x * blockDim.x + threadIdx.x;
    if (i >= n4) return;
    float4 v = ((const float4*)in)[i];
    __nv_bfloat16 h0 = __float2bfloat16(v.x);
    __nv_bfloat16 h1 = __float2bfloat16(v.y);
    __nv_bfloat16 h2 = __float2bfloat16(v.z);
    __nv_bfloat16 h3 = __float2bfloat16(v.w);
    __nv_bfloat16 l0 = __float2bfloat16(v.x - __bfloat162float(h0));
    __nv_bfloat16 l1 = __float2bfloat16(v.y - __bfloat162float(h1));
    __nv_bfloat16 l2 = __float2bfloat16(v.z - __bfloat162float(h2));
    __nv_bfloat16 l3 = __float2bfloat16(v.w - __bfloat162float(h3));
    __nv_bfloat162* H = (__nv_bfloat162*)hi;
    __nv_bfloat162* L = (__nv_bfloat162*)lo;
    H[2 * i]     = __nv_bfloat162(h0, h1);
    H[2 * i + 1] = __nv_bfloat162(h2, h3);
    L[2 * i]     = __nv_bfloat162(l0, l1);
    L[2 * i + 1] = __nv_bfloat162(l2, l3);
}

// ----------------------------------------------------------------------------
// mma.sync bf16 GEMM: C[r,n] = sum_k (Ah+Al)[r,k]*(Bh+Bl)[n,k] + bias[n]
// 3-term split: Ah*Bh + Ah*Bl + Al*Bh. 128x128 CTA tile, 8 warps (2m x 4n),
// warp tile 64x32 = 4x4 m16n8k16. BK=32, double-buffered cp.async.
// Column n scattered to region n/768 at region_stride (QKV q/k/v split).
// ----------------------------------------------------------------------------
__global__ __launch_bounds__(256) void mma_gemm_kernel(
    const __nv_bfloat16* __restrict__ Ah_, const __nv_bfloat16* __restrict__ Al_,
    const __nv_bfloat16* __restrict__ Bh_, const __nv_bfloat16* __restrict__ Bl_,
    const float* __restrict__ bias, float* __restrict__ C, size_t region_stride)
{
    extern __shared__ char smem[];
    const uint32_t sb = smem_u32(smem);
    const int tid = threadIdx.x;
    const int wid = tid >> 5;
    const int lane = tid & 31;
    const int wm = wid & 1;          // warp row (0..1) -> 64 rows
    const int wn = wid >> 1;         // warp col (0..3) -> 32 cols
    const int row0 = blockIdx.y * 128;
    const int col0 = blockIdx.x * 128;

    const char* gA_h = (const char*)(Ah_ + (size_t)row0 * GK);
    const char* gA_l = (const char*)(Al_ + (size_t)row0 * GK);
    const char* gB_h = (const char*)(Bh_ + (size_t)col0 * GK);
    const char* gB_l = (const char*)(Bl_ + (size_t)col0 * GK);

    // per-thread cp.async assignment: 2 granules per array
    const int r0g = (tid + 0)   >> 2, g0 = (tid + 0)   & 3;
    const int r1g = (tid + 256) >> 2, g1 = (tid + 256) & 3;

#define LOAD_CHUNK(kc, stage) do {                                          \
        const uint32_t s0_ = sb + (stage) * STAGE;                          \
        {                                                                   \
            uint32_t d = (uint32_t)r0g * TROW + g0 * 16;                    \
            size_t src = (size_t)r0g * (GK * 2) + (size_t)(kc) * 64 + g0 * 16; \
            CP_ASYNC16(s0_ + 0 * TBYTES + d, gA_h + src);                   \
            CP_ASYNC16(s0_ + 1 * TBYTES + d, gA_l + src);                   \
            CP_ASYNC16(s0_ + 2 * TBYTES + d, gB_h + src);                   \
            CP_ASYNC16(s0_ + 3 * TBYTES + d, gB_l + src);                   \
        }                                                                   \
        {                                                                   \
            uint32_t d = (uint32_t)r1g * TROW + g1 * 16;                    \
            size_t src = (size_t)r1g * (GK * 2) + (size_t)(kc) * 64 + g1 * 16; \
            CP_ASYNC16(s0_ + 0 * TBYTES + d, gA_h + src);                   \
            CP_ASYNC16(s0_ + 1 * TBYTES + d, gA_l + src);                   \
            CP_ASYNC16(s0_ + 2 * TBYTES + d, gB_h + src);                   \
            CP_ASYNC16(s0_ + 3 * TBYTES + d, gB_l + src);                   \
        }                                                                   \
        CP_COMMIT();                                                        \
    } while (0)

    float acc[4][4][4];
#pragma unroll
    for (int im = 0; im < 4; im++)
#pragma unroll
        for (int jn = 0; jn < 4; jn++)
#pragma unroll
            for (int q = 0; q < 4; q++) acc[im][jn][q] = 0.0f;

    // ldmatrix per-lane byte offsets within an array
    // A (x4): row = wm*64 + im*16 + (lane&7) + ((lane>>3)&1)*8, kcol = (lane>>4)*8
    const uint32_t aoff = (uint32_t)(wm * 64 + (lane & 7) + ((lane >> 3) & 1) * 8) * TROW
                        + (uint32_t)(lane >> 4) * 16;
    // B (x2, non-trans): lanes 0-7 -> n-rows (k0-7 piece), lanes 8-15 -> same
    // n-rows at +16B (k8-15 piece)
    const int l15 = lane & 15;
    const uint32_t boff = (uint32_t)(wn * 32 + (l15 & 7)) * TROW
                        + (uint32_t)((l15 >> 3) & 1) * 16;

    LOAD_CHUNK(0, 0);
    const int NKC = GK / 32;  // 24
    for (int kc = 0; kc < NKC; kc++) {
        if (kc + 1 < NKC) { LOAD_CHUNK(kc + 1, (kc + 1) & 1); CP_WAIT1(); }
        else              { CP_WAIT0(); }
        __syncthreads();

        const uint32_t s0 = sb + (kc & 1) * STAGE;
#pragma unroll
        for (int k16 = 0; k16 < 2; k16++) {
            const uint32_t kb = (uint32_t)k16 * 32;  // 16 cols * 2B
            uint32_t bh[4][2], bl[4][2];
#pragma unroll
            for (int jn = 0; jn < 4; jn++) {
                ldmx2(bh[jn], s0 + 2 * TBYTES + boff + jn * 8 * TROW + kb);
                ldmx2(bl[jn], s0 + 3 * TBYTES + boff + jn * 8 * TROW + kb);
            }
#pragma unroll
            for (int im = 0; im < 4; im++) {
                uint32_t ah[4], al[4];
                ldmx4(ah, s0 + 0 * TBYTES + aoff + im * 16 * TROW + kb);
                ldmx4(al, s0 + 1 * TBYTES + aoff + im * 16 * TROW + kb);
#pragma unroll
                for (int jn = 0; jn < 4; jn++) {
                    mma_bf16(acc[im][jn], ah, bh[jn]);
                    mma_bf16(acc[im][jn], ah, bl[jn]);
                    mma_bf16(acc[im][jn], al, bh[jn]);
                }
            }
        }
        __syncthreads();  // WAR guard: next iter's cp.async overwrites this buffer
    }

    // epilogue: direct register -> global stores with bias + region scatter
    const int gid = lane >> 2, tq = lane & 3;
#pragma unroll
    for (int jn = 0; jn < 4; jn++) {
        const int colg = col0 + wn * 32 + jn * 8 + tq * 2;
        const int region = colg / DMODEL;
        const int cc = colg - region * DMODEL;
        float* Cb = C + (size_t)region * region_stride + cc;
        const float bx = bias[colg], by = bias[colg + 1];
#pragma unroll
        for (int im = 0; im < 4; im++) {
            const int rg = row0 + wm * 64 + im * 16 + gid;
            float2 v0, v1;
            v0.x = acc[im][jn][0] + bx; v0.y = acc[im][jn][1] + by;
            v1.x = acc[im][jn][2] + bx; v1.y = acc[im][jn][3] + by;
            *(float2*)(Cb + (size_t)rg * DMODEL) = v0;
            *(float2*)(Cb + (size_t)(rg + 8) * DMODEL) = v1;
        }
    }
#undef LOAD_CHUNK
}

// ----------------------------------------------------------------------------
// Flash attention (math identical to the 1558us R4 version): 128 q-rows per
// block, 256 threads, shfl-only softmax reductions, 3 syncs per 64-key tile.
// Epilogue emits mix as bf16 hi/lo for the mma.sync out-projection.
// ----------------------------------------------------------------------------
__global__ __launch_bounds__(256, 2) void attn_kernel(
    const float* __restrict__ qg, const float* __restrict__ kg,
    const float* __restrict__ vg,
    __nv_bfloat16* __restrict__ mixh, __nv_bfloat16* __restrict__ mixl)
{
    extern __shared__ float sm[];
    float* Qs = sm;                    // [128][AST]
    float* Ks = Qs + 128 * AST;        // [64][AST]
    float* Vt = Ks + 64 * AST;         // [64][AST]
    float* Ps = Vt + 64 * AST;         // [128][AST]

    const int tid = threadIdx.x;
    const int tx = tid & 15;
    const int ty = tid >> 4;
    const int bh = blockIdx.y;
    const int b = bh / NHEAD;
    const int h = bh - b * NHEAD;
    const int q0 = blockIdx.x * 128;
    const size_t rstride = (size_t)BATCH * DMODEL;

    const float* qbase = qg + (size_t)q0 * rstride + (size_t)b * DMODEL + h * HDIM;
    const float* kbase = kg + (size_t)b * DMODEL + h * HDIM;
    const float* vbase = vg + (size_t)b * DMODEL + h * HDIM;

#pragma unroll
    for (int i = 0; i < 8; i++) {
        int f = tid + i * 256;
        int r = f >> 4, c4 = (f & 15) * 4;
        *(float4*)(Qs + r * AST + c4) = *(const float4*)(qbase + (size_t)r * rstride + c4);
    }

    float mrow[8], lrow[8], acc[8][4];
    bool qm[8];
#pragma unroll
    for (int i = 0; i < 8; i++) {
        mrow[i] = -1e30f; lrow[i] = 0.0f;
        int qr = q0 + ty * 8 + i;
        qm[i] = (qr == 0) || (qr >= TOKENS);
#pragma unroll
        for (int j = 0; j < 4; j++) acc[i][j] = 0.0f;
    }

    for (int kt = 0; kt < S_LEN; kt += 64) {
#pragma unroll
        for (int i = 0; i < 4; i++) {
            int f = tid + i * 256;
            int r = f >> 4, c4 = (f & 15) * 4;
            *(float4*)(Ks + r * AST + c4) =
                *(const float4*)(kbase + (size_t)(kt + r) * rstride + c4);
        }
#pragma unroll
        for (int i = 0; i < 4; i++) {
            int f = tid + i * 256;
            int r = f >> 4, c4 = (f & 15) * 4;
            float4 v = *(const float4*)(vbase + (size_t)(kt + r) * rstride + c4);
            Vt[(c4 + 0) * AST + r] = v.x;
            Vt[(c4 + 1) * AST + r] = v.y;
            Vt[(c4 + 2) * AST + r] = v.z;
            Vt[(c4 + 3) * AST + r] = v.w;
        }
        __syncthreads();

        float s[8][4];
#pragma unroll
        for (int i = 0; i < 8; i++)
#pragma unroll
            for (int j = 0; j < 4; j++) s[i][j] = 0.0f;

#pragma unroll
        for (int kk = 0; kk < HDIM; kk += 4) {
            float4 kf[4];
#pragma unroll
            for (int j = 0; j < 4; j++)
                kf[j] = *(const float4*)(Ks + (tx + j * 16) * AST + kk);
#pragma unroll
            for (int i = 0; i < 8; i++) {
                float4 qf = *(const float4*)(Qs + (ty * 8 + i) * AST + kk);
#pragma unroll
                for (int j = 0; j < 4; j++) {
                    s[i][j] = fmaf(qf.x, kf[j].x, s[i][j]);
                    s[i][j] = fmaf(qf.y, kf[j].y, s[i][j]);
                    s[i][j] = fmaf(qf.z, kf[j].z, s[i][j]);
                    s[i][j] = fmaf(qf.w, kf[j].w, s[i][j]);
                }
            }
        }

        float tm[8];
#pragma unroll
        for (int i = 0; i < 8; i++) {
            float m = -1e30f;
#pragma unroll
            for (int j = 0; j < 4; j++) {
                int kgl = kt + tx + j * 16;
                float v = s[i][j] * 0.125f;
                if (kgl >= TOKENS && qm[i]) v = -10000.0f;
                s[i][j] = v;
                m = fmaxf(m, v);
            }
            tm[i] = m;
        }
#pragma unroll
        for (int o = 1; o < 16; o <<= 1)
#pragma unroll
            for (int i = 0; i < 8; i++)
                tm[i] = fmaxf(tm[i], __shfl_xor_sync(0xffffffffu, tm[i], o));

        float psum[8];
#pragma unroll
        for (int i = 0; i < 8; i++) {
            float nm = fmaxf(mrow[i], tm[i]);
            float f = __expf(mrow[i] - nm);
            mrow[i] = nm;
            lrow[i] *= f;
#pragma unroll
            for (int j = 0; j < 4; j++) acc[i][j] *= f;
            float ps = 0.0f;
#pragma unroll
            for (int j = 0; j < 4; j++) {
                float p = __expf(s[i][j] - nm);
                Ps[(ty * 8 + i) * AST + tx + j * 16] = p;
                ps += p;
            }
            psum[i] = ps;
        }
#pragma unroll
        for (int o = 1; o < 16; o <<= 1)
#pragma unroll
            for (int i = 0; i < 8; i++)
                psum[i] += __shfl_xor_sync(0xffffffffu, psum[i], o);
#pragma unroll
        for (int i = 0; i < 8; i++) lrow[i] += psum[i];
        __syncthreads();

#pragma unroll
        for (int kk = 0; kk < 64; kk += 4) {
            float4 vf[4];
#pragma unroll
            for (int j = 0; j < 4; j++)
                vf[j] = *(const float4*)(Vt + (tx + j * 16) * AST + kk);
#pragma unroll
            for (int i = 0; i < 8; i++) {
                float4 pf = *(const float4*)(Ps + (ty * 8 + i) * AST + kk);
#pragma unroll
                for (int j = 0; j < 4; j++) {
                    acc[i][j] = fmaf(pf.x, vf[j].x, acc[i][j]);
                    acc[i][j] = fmaf(pf.y, vf[j].y, acc[i][j]);
                    acc[i][j] = fmaf(pf.z, vf[j].z, acc[i][j]);
                    acc[i][j] = fmaf(pf.w, vf[j].w, acc[i][j]);
                }
            }
        }
        __syncthreads();
    }

    // epilogue: normalize, split to bf16 hi/lo
#pragma unroll
    for (int i = 0; i < 8; i++) {
        int qr = q0 + ty * 8 + i;
        float inv = 1.0f / lrow[i];
        size_t base = ((size_t)qr * BATCH + b) * DMODEL + h * HDIM;
#pragma unroll
        for (int j = 0; j < 4; j++) {
            float o = acc[i][j] * inv;
            __nv_bfloat16 hh = __float2bfloat16(o);
            __nv_bfloat16 ll = __float2bfloat16(o - __bfloat162float(hh));
            mixh[base + tx + j * 16] = hh;
            mixl[base + tx + j * 16] = ll;
        }
    }
}

extern "C" void kernel_launch(void* const* d_in, const int* in_sizes, int n_in,
                              void* d_out, int out_size)
{
    const float* x      = (const float*)d_in[0];  // (S, B, D)
    const float* w_in   = (const float*)d_in[1];  // (3D, D)
    const float* b_in   = (const float*)d_in[2];  // (3D,)
    const float* w_out  = (const float*)d_in[3];  // (D, D)
    const float* b_out  = (const float*)d_in[4];  // (D,)
    float* out = (float*)d_out;

    float* q_out = out;            // q/k/v regions: [r=s*B+b][d]
    float* o_out = out + 3 * SBD;  // (S, B, D)

    __nv_bfloat16 *xh, *xl, *wih, *wil, *woh, *wol, *mixh, *mixl;
    cudaGetSymbolAddress((void**)&xh,   g_xh);
    cudaGetSymbolAddress((void**)&xl,   g_xl);
    cudaGetSymbolAddress((void**)&wih,  g_wih);
    cudaGetSymbolAddress((void**)&wil,  g_wil);
    cudaGetSymbolAddress((void**)&woh,  g_woh);
    cudaGetSymbolAddress((void**)&wol,  g_wol);
    cudaGetSymbolAddress((void**)&mixh, g_mixh);
    cudaGetSymbolAddress((void**)&mixl, g_mixl);

    const int gemm_smem = 2 * STAGE;  // 81920
    cudaFuncSetAttribute(mma_gemm_kernel, cudaFuncAttributeMaxDynamicSharedMemorySize, gemm_smem);

    // 0) fp32 -> bf16 hi/lo splits
    convert_split_kernel<<<(MROWS * GK / 4 + 255) / 256, 256>>>(x, xh, xl, MROWS * GK / 4);
    convert_split_kernel<<<(3 * DMODEL * GK / 4 + 255) / 256, 256>>>(w_in, wih, wil, 3 * DMODEL * GK / 4);
    convert_split_kernel<<<(DMODEL * GK / 4 + 255) / 256, 256>>>(w_out, woh, wol, DMODEL * GK / 4);

    // 1) QKV projection: M=8192, N=2304 -> q/k/v fp32 regions of d_out
    {
        dim3 grid(3 * DMODEL / 128, MROWS / 128);
        mma_gemm_kernel<<<grid, 256, gemm_smem>>>(xh, xl, wih, wil, b_in, q_out, SBD);
    }

    // 2) attention (fp32 in from d_out, bf16 hi/lo mix out)
    {
        int smem = (128 * AST + 64 * AST + 64 * AST + 128 * AST) * (int)sizeof(float);
        cudaFuncSetAttribute(attn_kernel, cudaFuncAttributeMaxDynamicSharedMemorySize, smem);
        dim3 grid(S_LEN / 128, BATCH * NHEAD);
        attn_kernel<<<grid, 256, smem>>>(q_out, q_out + SBD, q_out + 2 * SBD, mixh, mixl);
    }

    // 3) output projection: M=8192, N=768
    {
        dim3 grid(DMODEL / 128, MROWS / 128);
        mma_gemm_kernel<<<grid, 256, gemm_smem>>>(mixh, mixl, woh, wol, b_out, o_out, 0);
    }
}